// round 8
// baseline (speedup 1.0000x reference)
#include <cuda_runtime.h>
#include <cstdint>
#include <cstddef>

// Fixed shapes: B=1, N=1000, T=256, D=512, M=258, NUM=10
// out row = 3082 floats (12328 B; 16B-aligned only for even n)
#define N_CAND   1000
#define T_DIM    256
#define D_DIM    512
#define M_DIM    258
#define NUMF     10
#define ROW_OUT  3082
#define CPB      4                 // candidates per block
#define R4       (D_DIM / 4)       // 128 float4 per 512-float section

// 250 blocks x 256 threads. Each block handles 4 consecutive candidates.
// Thread t: half = t>>7 (which 3 sections), lane = t&127 (float4 lane).
// Per thread: 12 independent LDG.128 (front-batched -> ~6KB in flight per
// warp) followed by 12 stores. Store parity is compile-time per candidate j
// (block base is a multiple of 4, so j even => 16B-aligned row).
__global__ __launch_bounds__(256) void feature_gather_deep(
    const int* __restrict__ cand,        // [N,6]
    const float* __restrict__ num,       // [N,10]
    const float* __restrict__ blo,       // [N,T,D]
    const float* __restrict__ att,       // [N,M,D]
    float* __restrict__ out)             // [N,3082]
{
    const int n_base = blockIdx.x * CPB;
    const int t    = threadIdx.x;
    const int half = t >> 7;             // 0: sections 0..2, 1: sections 3..5
    const int lane = t & 127;

    // ---- indices for all 4 candidates (L1/L2 broadcast) ----
    int2 q0[CPB], q1[CPB], q2[CPB];      // (c0,c1) (c2,c3) (c4,c5)
    #pragma unroll
    for (int j = 0; j < CPB; j++) {
        const int2* cp = (const int2*)(cand + (n_base + j) * 6);
        q0[j] = __ldg(cp + 0);
        q1[j] = __ldg(cp + 1);
        q2[j] = __ldg(cp + 2);
    }

    // ---- front-batched gather loads: 12 independent LDG.128 ----
    float4 v[CPB][3];
    #pragma unroll
    for (int j = 0; j < CPB; j++) {
        const size_t n = n_base + j;
        const float4* b4 = (const float4*)(blo + n * (size_t)(T_DIM * D_DIM));
        const float4* a4 = (const float4*)(att + n * (size_t)(M_DIM * D_DIM));
        int rA, rB;               // blo rows for this half
        int rC;                   // att row for this half
        if (half == 0) { rA = q0[j].y; rB = q1[j].x; rC = q2[j].x; }        // c1,c2 | c4
        else           { rA = q2[j].y; rB = q0[j].x + 2; rC = q1[j].y + 2; } // c5 | c0+2,c3+2
        if (half == 0) {
            v[j][0] = __ldg(b4 + (size_t)rA * R4 + lane);   // sec 0 / 3
            v[j][1] = __ldg(b4 + (size_t)rB * R4 + lane);   // sec 1 / 4
            v[j][2] = __ldg(b4 + (size_t)rC * R4 + lane);   // sec 2 / 5
        } else {
            v[j][0] = __ldg(b4 + (size_t)rA * R4 + lane);
            v[j][1] = __ldg(a4 + (size_t)rB * R4 + lane);
            v[j][2] = __ldg(a4 + (size_t)rC * R4 + lane);
        }
    }

    // ---- stores: compile-time parity per j ----
    const int s0 = half * 3;
    #pragma unroll
    for (int j = 0; j < CPB; j++) {
        float* outRow = out + (size_t)(n_base + j) * ROW_OUT;
        if ((j & 1) == 0) {
            // even candidate: row base 16B-aligned -> float4 stores
            float4* o4 = (float4*)outRow;
            #pragma unroll
            for (int s = 0; s < 3; s++)
                o4[(s0 + s) * R4 + lane] = v[j][s];
        } else {
            // odd candidate: 8B-aligned -> float2 stores
            float2* o2 = (float2*)outRow;
            #pragma unroll
            for (int s = 0; s < 3; s++) {
                const int i = ((s0 + s) * R4 + lane) * 2;
                o2[i]     = make_float2(v[j][s].x, v[j][s].y);
                o2[i + 1] = make_float2(v[j][s].z, v[j][s].w);
            }
        }
    }

    // ---- numeric features: 4 candidates x 5 float2 = threads 0..19 ----
    if (t < CPB * (NUMF / 2)) {
        const int j = t / (NUMF / 2);
        const int k = t % (NUMF / 2);
        const float2* num2 = (const float2*)(num + (size_t)(n_base + j) * NUMF);
        float* outRow = out + (size_t)(n_base + j) * ROW_OUT;
        ((float2*)outRow)[6 * (D_DIM / 2) + k] = __ldg(num2 + k);
    }
}

extern "C" void kernel_launch(void* const* d_in, const int* in_sizes, int n_in,
                              void* d_out, int out_size) {
    const int*   cand = (const int*)d_in[0];
    const float* num  = (const float*)d_in[1];
    const float* blo  = (const float*)d_in[2];
    const float* att  = (const float*)d_in[3];
    float* out = (float*)d_out;

    feature_gather_deep<<<N_CAND / CPB, 256>>>(cand, num, blo, att, out);
}

// round 9
// speedup vs baseline: 1.0333x; 1.0333x over previous
#include <cuda_runtime.h>
#include <cstdint>
#include <cstddef>

// Fixed shapes: B=1, N=1000, T=256, D=512, M=258, NUM=10
// out row = 3082 floats (12328 B; 16B-aligned only for even n)
#define N_CAND   1000
#define T_DIM    256
#define D_DIM    512
#define M_DIM    258
#define NUMF     10
#define ROW_OUT  3082
#define R4       (D_DIM / 4)       // 128 float4 per section

// One block per candidate, 128 threads. Each thread copies float4 lane `t`
// of ALL six sections: 6 independent LDG.128 front-batched (MLP=6/thread,
// 3 KB in flight per warp), then 6 (or 12) stores by row parity.
__device__ __forceinline__ float4 ldg_nc_256(const float4* p) {
    float4 v;
    asm volatile("ld.global.nc.L2::256B.v4.f32 {%0,%1,%2,%3}, [%4];"
                 : "=f"(v.x), "=f"(v.y), "=f"(v.z), "=f"(v.w) : "l"(p));
    return v;
}

__global__ __launch_bounds__(128) void feature_gather_mlp6(
    const int* __restrict__ cand,        // [N,6]
    const float* __restrict__ num,       // [N,10]
    const float* __restrict__ blo,       // [N,T,D]
    const float* __restrict__ att,       // [N,M,D]
    float* __restrict__ out)             // [N,3082]
{
    const int n = blockIdx.x;
    const int t = threadIdx.x;           // float4 lane 0..127

    // Candidate indices (L2 broadcast, ~24 KB array stays L2-resident).
    const int2* cp = (const int2*)(cand + n * 6);
    const int2 p01 = __ldg(cp + 0);      // c0, c1
    const int2 p23 = __ldg(cp + 1);      // c2, c3
    const int2 p45 = __ldg(cp + 2);      // c4, c5

    const float4* b4 = (const float4*)(blo + (size_t)n * T_DIM * D_DIM);
    const float4* a4 = (const float4*)(att + (size_t)n * M_DIM * D_DIM);

    // Six independent gather loads, front-batched.
    const float4 v0 = ldg_nc_256(b4 + (size_t)p01.y * R4 + t);        // blo[c1]
    const float4 v1 = ldg_nc_256(b4 + (size_t)p23.x * R4 + t);        // blo[c2]
    const float4 v2 = ldg_nc_256(b4 + (size_t)p45.x * R4 + t);        // blo[c4]
    const float4 v3 = ldg_nc_256(b4 + (size_t)p45.y * R4 + t);        // blo[c5]
    const float4 v4 = ldg_nc_256(a4 + (size_t)(p01.x + 2) * R4 + t);  // att[c0+2]
    const float4 v5 = ldg_nc_256(a4 + (size_t)(p23.y + 2) * R4 + t);  // att[c3+2]

    float* outRow = out + (size_t)n * ROW_OUT;

    if ((n & 1) == 0) {
        float4* o4 = (float4*)outRow;    // 16B-aligned row
        o4[0 * R4 + t] = v0;
        o4[1 * R4 + t] = v1;
        o4[2 * R4 + t] = v2;
        o4[3 * R4 + t] = v3;
        o4[4 * R4 + t] = v4;
        o4[5 * R4 + t] = v5;
    } else {
        float2* o2 = (float2*)outRow;    // 8B-aligned row
        #define ST2(s, v)                                            \
            o2[((s) * R4 + t) * 2]     = make_float2((v).x, (v).y);  \
            o2[((s) * R4 + t) * 2 + 1] = make_float2((v).z, (v).w);
        ST2(0, v0) ST2(1, v1) ST2(2, v2) ST2(3, v3) ST2(4, v4) ST2(5, v5)
        #undef ST2
    }

    // Numeric features: 10 floats = 5 float2, threads 0..4.
    if (t < NUMF / 2) {
        const float2* num2 = (const float2*)(num + (size_t)n * NUMF);
        ((float2*)outRow)[6 * (D_DIM / 2) + t] = __ldg(num2 + t);
    }
}

extern "C" void kernel_launch(void* const* d_in, const int* in_sizes, int n_in,
                              void* d_out, int out_size) {
    const int*   cand = (const int*)d_in[0];
    const float* num  = (const float*)d_in[1];
    const float* blo  = (const float*)d_in[2];
    const float* att  = (const float*)d_in[3];
    float* out = (float*)d_out;

    feature_gather_mlp6<<<N_CAND, 128>>>(cand, num, blo, att, out);
}